// round 17
// baseline (speedup 1.0000x reference)
#include <cuda_runtime.h>
#include <cuda_bf16.h>
#include <cuda_fp16.h>
#include <math.h>

#define SEQ 2048
#define ND  128
#define NH  24
#define NC  32
#define PI2 6.283185307179586f

typedef unsigned long long u64;
typedef unsigned int u32;

__device__ float  g_k[NH*NC*SEQ];     // [h][c][i]
__device__ float  g_q[NH*NC*SEQ];     // [h][c][j]
__device__ u64    g_qp[NH*64*512];    // bf16 q B-frags (hi 256 / lo 256 per chunk)
__device__ u64    g_vp[NH*64*1024];   // fp16 v B-frags (k16)
__device__ u64    g_na[128*8*4*32];   // nodes bf16 hi/lo A-frags
__device__ u64    g_wb[384*8*2*32];   // w_values bf16 hi/lo B-frags
__device__ u64    g_wkq[64*8*2*32];   // w_nodes_kq bf16 hi/lo B-frags
__device__ __half g_part[NH*SEQ*ND];  // fp16 per-head partials

__device__ __forceinline__ u32 bf2(float lo, float hi){
    u32 r; asm("cvt.rn.bf16x2.f32 %0,%1,%2;" : "=r"(r) : "f"(hi), "f"(lo)); return r;
}
__device__ __forceinline__ u32 hf2(float lo, float hi){
    __half2 h = __floats2half2_rn(lo, hi);
    return *(u32*)&h;
}
__device__ __forceinline__ float bfr(float x){ return __bfloat162float(__float2bfloat16_rn(x)); }

__device__ __forceinline__ void mma16b(float* c, const u32* a, u32 b0, u32 b1){
    asm volatile("mma.sync.aligned.m16n8k16.row.col.f32.bf16.bf16.f32 "
        "{%0,%1,%2,%3},{%4,%5,%6,%7},{%8,%9},{%0,%1,%2,%3};"
        : "+f"(c[0]),"+f"(c[1]),"+f"(c[2]),"+f"(c[3])
        : "r"(a[0]),"r"(a[1]),"r"(a[2]),"r"(a[3]),"r"(b0),"r"(b1));
}
__device__ __forceinline__ void mma16h(float* c, const u32* a, u32 b0, u32 b1){
    asm volatile("mma.sync.aligned.m16n8k16.row.col.f32.f16.f16.f32 "
        "{%0,%1,%2,%3},{%4,%5,%6,%7},{%8,%9},{%0,%1,%2,%3};"
        : "+f"(c[0]),"+f"(c[1]),"+f"(c[2]),"+f"(c[3])
        : "r"(a[0]),"r"(a[1]),"r"(a[2]),"r"(a[3]),"r"(b0),"r"(b1));
}

__device__ __forceinline__ void cpa16(void* smem, const void* gmem){
    u32 s = (u32)__cvta_generic_to_shared(smem);
    asm volatile("cp.async.cg.shared.global [%0], [%1], 16;" :: "r"(s), "l"(gmem));
}
#define CP_COMMIT() asm volatile("cp.async.commit_group;")
#define CP_WAIT1()  asm volatile("cp.async.wait_group 1;")
#define CP_WAIT0()  asm volatile("cp.async.wait_group 0;")

// ---- pack a row-major [Ox128] weight into bf16 hi/lo B-frags (device helper) ----
__device__ __forceinline__ void pack_w_one(const float* __restrict__ w, u64* __restrict__ dst, int id)
{
    int lane = id&31, kt = (id>>5)&7, nt = id>>8;
    int g = lane>>2, tig = lane&3;
    int o = nt*8+g, c0 = kt*16+2*tig;
    float2 wa = *(const float2*)&w[o*128 + c0];
    float2 wb = *(const float2*)&w[o*128 + c0+8];
    float ha0=bfr(wa.x), ha1=bfr(wa.y), hb0=bfr(wb.x), hb1=bfr(wb.y);
    size_t base = (size_t)(nt*8+kt)*2*32 + lane;
    dst[base]    = ((u64)bf2(hb0,hb1)<<32) | bf2(ha0,ha1);
    dst[base+32] = ((u64)bf2(wb.x-hb0,wb.y-hb1)<<32) | bf2(wa.x-ha0,wa.y-ha1);
}

// ---- fused prep: pack_nodes | pack_wb | pack_wkq | proj_kq_pr, by block range ----
__global__ __launch_bounds__(256) void prep_kernel(
    const float* __restrict__ nodes, const float* __restrict__ w_values,
    const float* __restrict__ w_nodes_kq,
    const float* __restrict__ pos, const float* __restrict__ rot,
    const float* __restrict__ w_pos, const float* __restrict__ b_pos,
    const float* __restrict__ w_rot)
{
    const int bid = blockIdx.x, tid = threadIdx.x;

    if (bid < 128) {            // pack nodes A-frags
        int id = bid*256 + tid;
        int lane = id&31, kt = (id>>5)&7, jt = id>>8;
        int g = lane>>2, tig = lane&3;
        int r0 = jt*16+g, c0 = kt*16+2*tig;
        float2 v00 = *(const float2*)&nodes[r0*128 + c0];
        float2 v10 = *(const float2*)&nodes[(r0+8)*128 + c0];
        float2 v01 = *(const float2*)&nodes[r0*128 + c0+8];
        float2 v11 = *(const float2*)&nodes[(r0+8)*128 + c0+8];
        float h00=bfr(v00.x), h01=bfr(v00.y), h10=bfr(v10.x), h11=bfr(v10.y);
        float h20=bfr(v01.x), h21=bfr(v01.y), h30=bfr(v11.x), h31=bfr(v11.y);
        size_t base = (size_t)(jt*8+kt)*4*32 + lane;
        g_na[base]    = ((u64)bf2(h10,h11)<<32) | bf2(h00,h01);
        g_na[base+32] = ((u64)bf2(h30,h31)<<32) | bf2(h20,h21);
        g_na[base+64] = ((u64)bf2(v10.x-h10,v10.y-h11)<<32) | bf2(v00.x-h00,v00.y-h01);
        g_na[base+96] = ((u64)bf2(v11.x-h30,v11.y-h31)<<32) | bf2(v01.x-h20,v01.y-h21);
        return;
    }
    if (bid < 512) {            // w_values -> g_wb
        pack_w_one(w_values, g_wb, (bid-128)*256 + tid);
        return;
    }
    if (bid < 576) {            // w_nodes_kq -> g_wkq
        pack_w_one(w_nodes_kq, g_wkq, (bid-512)*256 + tid);
        return;
    }

    // proj_kq_pr: pos/rot heads 8..23
    __shared__ float sp[16][6], sr[16][4];
    const int i0 = (bid-576)*16;
    if (tid < 16) {
        int i = i0 + tid;
        float p0 = pos[i*3], p1 = pos[i*3+1], p2 = pos[i*3+2];
        sp[tid][0]=cosf(PI2*p0); sp[tid][1]=cosf(PI2*p1); sp[tid][2]=cosf(PI2*p2);
        sp[tid][3]=sinf(PI2*p0); sp[tid][4]=sinf(PI2*p1); sp[tid][5]=sinf(PI2*p2);
        sr[tid][0]=rot[i*4]; sr[tid][1]=rot[i*4+1]; sr[tid][2]=rot[i*4+2]; sr[tid][3]=rot[i*4+3];
    }
    __syncthreads();

    for (int o = tid; o < 512; o += 256) {
        float acc[16], b = b_pos[o];
        #pragma unroll
        for (int r = 0; r < 16; r++) acc[r] = b;
        const float* w = w_pos + o*6;
        for (int kk = 0; kk < 6; kk++) {
            float wv = __ldg(w+kk);
            #pragma unroll
            for (int r = 0; r < 16; r++) acc[r] += wv * sp[r][kk];
        }
        int hh = (o>>6)+8, cx = o&63;
        float* dst = ((cx<32)?g_k:g_q) + (hh*NC + (cx&31))*SEQ + i0;
        #pragma unroll
        for (int r4 = 0; r4 < 4; r4++)
            ((float4*)dst)[r4] = make_float4(acc[4*r4],acc[4*r4+1],acc[4*r4+2],acc[4*r4+3]);
    }
    for (int o = tid; o < 512; o += 256) {
        float acc[16];
        #pragma unroll
        for (int r = 0; r < 16; r++) acc[r] = 0.f;
        const float* w = w_rot + o*4;
        for (int kk = 0; kk < 4; kk++) {
            float wv = __ldg(w+kk);
            #pragma unroll
            for (int r = 0; r < 16; r++) acc[r] += wv * sr[r][kk];
        }
        int hh = (o>>6)+16, cx = o&63;
        float* dst = ((cx<32)?g_k:g_q) + (hh*NC + (cx&31))*SEQ + i0;
        #pragma unroll
        for (int r4 = 0; r4 < 4; r4++)
            ((float4*)dst)[r4] = make_float4(acc[4*r4],acc[4*r4+1],acc[4*r4+2],acc[4*r4+3]);
    }
}

// nodes k/q projection (heads 0..7) as 3-pass split-bf16 mma GEMM
#define KQ_SMEM (16384 + 65536)
__global__ __launch_bounds__(256) void proj_kq_mma(const float* __restrict__ bias)
{
    extern __shared__ __align__(16) unsigned char sm[];
    u64* sA = (u64*)sm;
    u64* sB = (u64*)(sm + 16384);
    float* sO = (float*)(sm + 16384);    // overlaps sB after mainloop

    const int tid = threadIdx.x, w = tid>>5, lane = tid&31;
    const int g = lane>>2, tig = lane&3;
    const int jb = blockIdx.x, oy = blockIdx.y;
    const int jw = w>>2, dw = w&3;

    const float4* srcA = (const float4*)(g_na + (size_t)(jb*2)*8*4*32);
    for (int f = tid; f < 1024; f += 256) cpa16((float4*)sA + f, srcA + f);
    const float4* srcB = (const float4*)(g_wkq + (size_t)oy*16*8*2*32);
    for (int f = tid; f < 4096; f += 256) cpa16((float4*)sB + f, srcB + f);
    CP_COMMIT();
    CP_WAIT0();
    __syncthreads();

    float acc[4][4];
    #pragma unroll
    for (int nt = 0; nt < 4; nt++) { acc[nt][0]=0.f; acc[nt][1]=0.f; acc[nt][2]=0.f; acc[nt][3]=0.f; }

    const u64* A = sA + (size_t)jw*(8*4*32);
    const u64* B = sB + (size_t)dw*4*(8*2*32);
    #pragma unroll
    for (int kt = 0; kt < 8; kt++) {
        u64 h01 = A[(kt*4+0)*32+lane], h23 = A[(kt*4+1)*32+lane];
        u64 l01 = A[(kt*4+2)*32+lane], l23 = A[(kt*4+3)*32+lane];
        u32 ah[4] = {(u32)h01,(u32)(h01>>32),(u32)h23,(u32)(h23>>32)};
        u32 al[4] = {(u32)l01,(u32)(l01>>32),(u32)l23,(u32)(l23>>32)};
        #pragma unroll
        for (int nt = 0; nt < 4; nt++) {
            u64 bh = B[((nt*8+kt)*2+0)*32+lane];
            u64 bl = B[((nt*8+kt)*2+1)*32+lane];
            mma16b(acc[nt], ah, (u32)bh, (u32)(bh>>32));
            mma16b(acc[nt], al, (u32)bh, (u32)(bh>>32));
            mma16b(acc[nt], ah, (u32)bl, (u32)(bl>>32));
        }
    }
    __syncthreads();

    #pragma unroll
    for (int nt = 0; nt < 4; nt++) {
        int d = dw*32 + nt*8 + 2*tig;
        int o = oy*128 + d;
        float b0 = __ldg(&bias[o]), b1 = __ldg(&bias[o+1]);
        int j0 = jw*16 + g;
        sO[j0*133 + d]       = acc[nt][0] + b0;
        sO[j0*133 + d + 1]   = acc[nt][1] + b1;
        sO[(j0+8)*133 + d]   = acc[nt][2] + b0;
        sO[(j0+8)*133 + d+1] = acc[nt][3] + b1;
    }
    __syncthreads();

    for (int f = tid; f < 4096; f += 256) {
        int ol = f >> 5, j = f & 31;
        int o = oy*128 + ol;
        int hh = o >> 6, cx = o & 63;
        float* dst = ((cx < 32) ? g_k : g_q) + (size_t)(hh*NC + (cx & 31))*SEQ + jb*32 + j;
        *dst = sO[j*133 + ol];
    }
}

// values projection as 3-pass split-bf16 mma GEMM, writing g_vp frags directly
#define PV_SMEM (16384 + 65536 + 8448)
__global__ __launch_bounds__(256) void proj_val_mma(const float* __restrict__ b_values)
{
    extern __shared__ __align__(16) unsigned char sm[];
    u64* sA = (u64*)sm;
    u64* sB = (u64*)(sm + 16384);
    __half* sO = (__half*)(sm + 81920);   // [32 j][132]

    const int tid = threadIdx.x, w = tid>>5, lane = tid&31;
    const int g = lane>>2, tig = lane&3;
    const int jb = blockIdx.x, h = blockIdx.y;
    const int jw = w>>2, dw = w&3;

    const float4* srcA = (const float4*)(g_na + (size_t)(jb*2)*8*4*32);
    for (int f = tid; f < 1024; f += 256) cpa16((float4*)sA + f, srcA + f);
    const float4* srcB = (const float4*)(g_wb + (size_t)h*16*8*2*32);
    for (int f = tid; f < 4096; f += 256) cpa16((float4*)sB + f, srcB + f);
    CP_COMMIT();
    CP_WAIT0();
    __syncthreads();

    float acc[4][4];
    #pragma unroll
    for (int nt = 0; nt < 4; nt++) { acc[nt][0]=0.f; acc[nt][1]=0.f; acc[nt][2]=0.f; acc[nt][3]=0.f; }

    const u64* A = sA + (size_t)jw*(8*4*32);
    const u64* B = sB + (size_t)dw*4*(8*2*32);
    #pragma unroll
    for (int kt = 0; kt < 8; kt++) {
        u64 h01 = A[(kt*4+0)*32+lane], h23 = A[(kt*4+1)*32+lane];
        u64 l01 = A[(kt*4+2)*32+lane], l23 = A[(kt*4+3)*32+lane];
        u32 ah[4] = {(u32)h01,(u32)(h01>>32),(u32)h23,(u32)(h23>>32)};
        u32 al[4] = {(u32)l01,(u32)(l01>>32),(u32)l23,(u32)(l23>>32)};
        #pragma unroll
        for (int nt = 0; nt < 4; nt++) {
            u64 bh = B[((nt*8+kt)*2+0)*32+lane];
            u64 bl = B[((nt*8+kt)*2+1)*32+lane];
            mma16b(acc[nt], ah, (u32)bh, (u32)(bh>>32));
            mma16b(acc[nt], al, (u32)bh, (u32)(bh>>32));
            mma16b(acc[nt], ah, (u32)bl, (u32)(bl>>32));
        }
    }

    #pragma unroll
    for (int nt = 0; nt < 4; nt++) {
        int d = dw*32 + nt*8 + 2*tig;
        float b0 = __ldg(&b_values[h*128 + d]);
        float b1 = __ldg(&b_values[h*128 + d + 1]);
        int j0 = jw*16 + g;
        *(__half2*)&sO[j0*132 + d]     = __floats2half2_rn(acc[nt][0]+b0, acc[nt][1]+b1);
        *(__half2*)&sO[(j0+8)*132 + d] = __floats2half2_rn(acc[nt][2]+b0, acc[nt][3]+b1);
    }
    __syncthreads();

    u64* dst = g_vp + ((size_t)h*64 + jb)*1024;
    #pragma unroll
    for (int q = 0; q < 4; q++) {
        int f = tid*4 + q;
        int lv = f&31, ntv = (f>>5)&15, ktv = f>>9;
        int gv = lv>>2, tv = lv&3;
        int d = ntv*8 + gv, j = ktv*16;
        __half2 x = __halves2half2(sO[(j+2*tv)*132+d],   sO[(j+2*tv+1)*132+d]);
        __half2 y = __halves2half2(sO[(j+2*tv+8)*132+d], sO[(j+2*tv+9)*132+d]);
        dst[f] = ((u64)(*(u32*)&y)<<32) | (*(u32*)&x);
    }
}

__global__ __launch_bounds__(256) void pack_qb_kernel()
{
    int id = blockIdx.x*256 + threadIdx.x;
    int lane = id&31, nt = (id>>5)&3, kt = (id>>7)&1, ch = (id>>8)&63, h = id>>14;
    int g = lane>>2, tig = lane&3;
    int c0 = kt*16 + 2*tig, j = ch*32 + nt*8 + g;
    float q00 = g_q[(h*NC+c0  )*SEQ + j];
    float q01 = g_q[(h*NC+c0+1)*SEQ + j];
    float q08 = g_q[(h*NC+c0+8)*SEQ + j];
    float q09 = g_q[(h*NC+c0+9)*SEQ + j];
    float h00 = bfr(q00), h01 = bfr(q01), h08 = bfr(q08), h09 = bfr(q09);
    u32 hx = bf2(h00, h01), hy = bf2(h08, h09);
    u32 lx = bf2(q00-h00, q01-h01), ly = bf2(q08-h08, q09-h09);
    size_t base = ((size_t)h*64 + ch)*512 + kt*128 + nt*32 + lane;
    g_qp[base]       = ((u64)hy<<32) | hx;
    g_qp[base + 256] = ((u64)ly<<32) | lx;
}

// attention: 64 rows/block, 4 warps; QK bf16 3-pass, PV fp16 k16 single-pass
#define SMEM_DYN (2*4096 + 2*8192 + 4*1152)
__global__ __launch_bounds__(128) void attn_kernel()
{
    extern __shared__ __align__(16) unsigned char dsm[];
    u64* qbuf = (u64*)dsm;                 // 2 x 512 u64
    u64* vbuf = (u64*)(dsm + 8192);        // 2 x 1024 u64

    const int tid = threadIdx.x, w = tid>>5, lane = tid&31;
    const int g = lane>>2, tig = lane&3;
    const int h = blockIdx.y, i0 = blockIdx.x*64, iw = i0 + 16*w;
    u32* pP = (u32*)(dsm + 24576) + w*288; // [16][18] u32 per warp

    u32 ah[2][4], al[2][4];
    #pragma unroll
    for (int kt = 0; kt < 2; kt++) {
        int c0 = kt*16 + 2*tig;
        float kv[4][2];
        #pragma unroll
        for (int e = 0; e < 4; e++) {
            int c = c0 + (e>>1)*8;
            int i = iw + g + (e&1)*8;
            kv[e][0] = g_k[(h*NC + c)*SEQ + i];
            kv[e][1] = g_k[(h*NC + c+1)*SEQ + i];
        }
        #pragma unroll
        for (int e = 0; e < 4; e++) {
            float h0 = bfr(kv[e][0]);
            float h1 = bfr(kv[e][1]);
            ah[kt][e] = bf2(h0, h1);
            al[kt][e] = bf2(kv[e][0]-h0, kv[e][1]-h1);
        }
    }

    float o[16][4];
    #pragma unroll
    for (int nt = 0; nt < 16; nt++) { o[nt][0]=0.f; o[nt][1]=0.f; o[nt][2]=0.f; o[nt][3]=0.f; }
    float m0 = -1e30f, m1 = -1e30f, s0 = 0.f, s1 = 0.f;

    const u64* gqp = g_qp + (size_t)h*64*512;
    const u64* gvp = g_vp + (size_t)h*64*1024;
    const bool sqh = (h >= 16);

    {
        #pragma unroll
        for (int r = 0; r < 2; r++) cpa16((float4*)qbuf + tid + 128*r, (const float4*)gqp + tid + 128*r);
        #pragma unroll
        for (int r = 0; r < 4; r++) cpa16((float4*)vbuf + tid + 128*r, (const float4*)gvp + tid + 128*r);
        CP_COMMIT();
    }

    for (int ch = 0; ch < 64; ch++) {
        int cur = ch & 1;
        if (ch < 63) {
            int nb = (ch+1) & 1;
            const float4* sq = (const float4*)(gqp + (size_t)(ch+1)*512);
            const float4* sv = (const float4*)(gvp + (size_t)(ch+1)*1024);
            #pragma unroll
            for (int r = 0; r < 2; r++) cpa16((float4*)(qbuf + nb*512) + tid + 128*r, sq + tid + 128*r);
            #pragma unroll
            for (int r = 0; r < 4; r++) cpa16((float4*)(vbuf + nb*1024) + tid + 128*r, sv + tid + 128*r);
        }
        CP_COMMIT();
        CP_WAIT1();
        __syncthreads();

        const u64* sqp = qbuf + cur*512;
        const u64* svp = vbuf + cur*1024;

        float C[4][4];
        #pragma unroll
        for (int nt = 0; nt < 4; nt++) { C[nt][0]=0.f; C[nt][1]=0.f; C[nt][2]=0.f; C[nt][3]=0.f; }
        #pragma unroll
        for (int kt = 0; kt < 2; kt++) {
            #pragma unroll
            for (int nt = 0; nt < 4; nt++) {
                u64 bh = sqp[kt*128 + nt*32 + lane];
                u64 bl = sqp[256 + kt*128 + nt*32 + lane];
                u32 bh0 = (u32)bh, bh1 = (u32)(bh>>32);
                mma16b(C[nt], ah[kt], bh0, bh1);
                mma16b(C[nt], al[kt], bh0, bh1);
                mma16b(C[nt], ah[kt], (u32)bl, (u32)(bl>>32));
            }
        }
        if (sqh) {
            #pragma unroll
            for (int nt = 0; nt < 4; nt++) {
                C[nt][0]*=C[nt][0]; C[nt][1]*=C[nt][1]; C[nt][2]*=C[nt][2]; C[nt][3]*=C[nt][3];
            }
        }

        float cm0 = -1e30f, cm1 = -1e30f;
        #pragma unroll
        for (int nt = 0; nt < 4; nt++) {
            cm0 = fmaxf(cm0, fmaxf(C[nt][0], C[nt][1]));
            cm1 = fmaxf(cm1, fmaxf(C[nt][2], C[nt][3]));
        }
        cm0 = fmaxf(cm0, __shfl_xor_sync(0xffffffffu, cm0, 1));
        cm0 = fmaxf(cm0, __shfl_xor_sync(0xffffffffu, cm0, 2));
        cm1 = fmaxf(cm1, __shfl_xor_sync(0xffffffffu, cm1, 1));
        cm1 = fmaxf(cm1, __shfl_xor_sync(0xffffffffu, cm1, 2));
        float nm0 = fmaxf(m0, cm0), nm1 = fmaxf(m1, cm1);
        bool noup = (nm0 == m0) & (nm1 == m1);
        float ca0 = __expf(m0 - nm0), ca1 = __expf(m1 - nm1);
        m0 = nm0; m1 = nm1;

        float p[4][4];
        float cs0 = 0.f, cs1 = 0.f;
        #pragma unroll
        for (int nt = 0; nt < 4; nt++) {
            p[nt][0] = __expf(C[nt][0] - nm0);
            p[nt][1] = __expf(C[nt][1] - nm0);
            p[nt][2] = __expf(C[nt][2] - nm1);
            p[nt][3] = __expf(C[nt][3] - nm1);
            cs0 += p[nt][0] + p[nt][1];
            cs1 += p[nt][2] + p[nt][3];
        }
        cs0 += __shfl_xor_sync(0xffffffffu, cs0, 1);
        cs0 += __shfl_xor_sync(0xffffffffu, cs0, 2);
        cs1 += __shfl_xor_sync(0xffffffffu, cs1, 1);
        cs1 += __shfl_xor_sync(0xffffffffu, cs1, 2);
        s0 = s0*ca0 + cs0;
        s1 = s1*ca1 + cs1;
        if (!__all_sync(0xffffffffu, noup)) {
            #pragma unroll
            for (int nt = 0; nt < 16; nt++) {
                o[nt][0] *= ca0; o[nt][1] *= ca0;
                o[nt][2] *= ca1; o[nt][3] *= ca1;
            }
        }

        #pragma unroll
        for (int nt = 0; nt < 4; nt++) {
            pP[g*18     + nt*4 + tig] = hf2(p[nt][0], p[nt][1]);
            pP[(g+8)*18 + nt*4 + tig] = hf2(p[nt][2], p[nt][3]);
        }
        __syncwarp();
        u32 pa[2][4];
        #pragma unroll
        for (int kt = 0; kt < 2; kt++) {
            pa[kt][0] = pP[g*18     + kt*8 + tig];
            pa[kt][1] = pP[(g+8)*18 + kt*8 + tig];
            pa[kt][2] = pP[g*18     + kt*8 + tig + 4];
            pa[kt][3] = pP[(g+8)*18 + kt*8 + tig + 4];
        }

        #pragma unroll
        for (int kt = 0; kt < 2; kt++) {
            #pragma unroll
            for (int nt = 0; nt < 16; nt++) {
                u64 bv = svp[kt*512 + nt*32 + lane];
                mma16h(o[nt], pa[kt], (u32)bv, (u32)(bv>>32));
            }
        }
        __syncthreads();
    }

    float inv0 = 1.f/s0, inv1 = 1.f/s1;
    __half* gp = g_part + ((size_t)h*SEQ + iw)*ND;
    #pragma unroll
    for (int nt = 0; nt < 16; nt++) {
        *(__half2*)&gp[(size_t)g*ND + nt*8 + 2*tig]     = __floats2half2_rn(o[nt][0]*inv0, o[nt][1]*inv0);
        *(__half2*)&gp[(size_t)(g+8)*ND + nt*8 + 2*tig] = __floats2half2_rn(o[nt][2]*inv1, o[nt][3]*inv1);
    }
}

__global__ __launch_bounds__(256) void reduce_kernel(float* __restrict__ out)
{
    int idx = blockIdx.x*256 + threadIdx.x;
    const u32* gp = (const u32*)g_part;
    float2 s = make_float2(0.f, 0.f);
    #pragma unroll
    for (int hh = 0; hh < NH; hh++) {
        u32 v = gp[(size_t)hh*(SEQ*ND/2) + idx];
        float2 f = __half22float2(*(__half2*)&v);
        s.x += f.x; s.y += f.y;
    }
    ((float2*)out)[idx] = s;
}

extern "C" void kernel_launch(void* const* d_in, const int* in_sizes, int n_in,
                              void* d_out, int out_size)
{
    const float* nodes = (const float*)d_in[0];

    cudaFuncSetAttribute(proj_kq_mma,  cudaFuncAttributeMaxDynamicSharedMemorySize, KQ_SMEM);
    cudaFuncSetAttribute(proj_val_mma, cudaFuncAttributeMaxDynamicSharedMemorySize, PV_SMEM);
    cudaFuncSetAttribute(attn_kernel,  cudaFuncAttributeMaxDynamicSharedMemorySize, SMEM_DYN);

    cudaStream_t s1;
    cudaStreamCreateWithFlags(&s1, cudaStreamNonBlocking);
    cudaEvent_t eP, e1;
    cudaEventCreateWithFlags(&eP, cudaEventDisableTiming);
    cudaEventCreateWithFlags(&e1, cudaEventDisableTiming);

    // fused prep (all roots)
    prep_kernel<<<704, 256>>>(nodes, (const float*)d_in[8], (const float*)d_in[3],
                              (const float*)d_in[1], (const float*)d_in[2],
                              (const float*)d_in[5], (const float*)d_in[6],
                              (const float*)d_in[7]);
    cudaEventRecord(eP, 0);

    // stream 0: proj_val
    dim3 gpv(64, NH);
    proj_val_mma<<<gpv, 256, PV_SMEM>>>((const float*)d_in[9]);

    // stream 1: proj_kq_mma (after prep)
    cudaStreamWaitEvent(s1, eP, 0);
    dim3 gkq(64, 4);
    proj_kq_mma<<<gkq, 256, KQ_SMEM, s1>>>((const float*)d_in[4]);
    cudaEventRecord(e1, s1);

    // join: pack_qb needs proj_kq_mma (s1) + proj_kq_pr (in prep, stream 0 order)
    cudaStreamWaitEvent(0, e1, 0);
    pack_qb_kernel<<<1536, 256>>>();

    dim3 ga(SEQ/64, NH);
    attn_kernel<<<ga, 128, SMEM_DYN>>>();
    reduce_kernel<<<(SEQ*ND/2)/256, 256>>>((float*)d_out);

    cudaStreamDestroy(s1);
    cudaEventDestroy(eP);
    cudaEventDestroy(e1);
}